// round 16
// baseline (speedup 1.0000x reference)
#include <cuda_runtime.h>
#include <cuda_bf16.h>
#include <mma.h>
#include <math.h>
#include <stdint.h>

using namespace nvcuda;

#define TT    256
#define IN_F  1024
#define HID_F 1024
#define OUT_F 1024
#define BB    128
#define HB    (HID_F * BB)
#define KDIM  1024
#define CH    32          // K chunk (outer GEMMs)
#define KPA   40          // outer GEMM A smem k-pitch
#define KPB   136         // B smem pitch (elements)

// outer gemm dynamic smem: 2 stages x (Ah+Al+Bh+Bl)
#define A_BYTES   (128 * KPA * 2)             // 10240
#define B_BYTES   (CH * KPB * 2)              // 8704
#define STG_BYTES (2 * A_BYTES + 2 * B_BYTES) // 37888
#define GSMEM     (2 * STG_BYTES)             // 75776

// step kernel dynamic smem: W-resident (hi+lo) + 2 B stages (hi+lo)
#define S_W_BYTES (64 * 136 * 2)              // 17408 per array
#define S_B_BYTES (32 * 136 * 2)              // 8704 per array
#define S_STG     (2 * S_B_BYTES)             // 17408 per stage
#define SSMEM     (2 * S_W_BYTES + 2 * S_STG) // 69632

// Scratch (__device__ globals; no allocations allowed)
__device__ float g_S[(size_t)TT * HB];
__device__ __nv_bfloat16 g_Xhi[(size_t)TT * HB];
__device__ __nv_bfloat16 g_Xlo[(size_t)TT * HB];
__device__ __nv_bfloat16 g_W1hi[(size_t)HID_F * IN_F];
__device__ __nv_bfloat16 g_W1lo[(size_t)HID_F * IN_F];
__device__ __nv_bfloat16 g_W2hi[(size_t)OUT_F * HID_F];
__device__ __nv_bfloat16 g_W2lo[(size_t)OUT_F * HID_F];
__device__ __nv_bfloat16 g_WHhi[(size_t)HID_F * HID_F];
__device__ __nv_bfloat16 g_WHlo[(size_t)HID_F * HID_F];

// ---------------------------------------------------------------------------
__device__ __forceinline__ void red_add_v4(float* p, float a, float b,
                                           float c, float d)
{
    asm volatile("red.global.add.v4.f32 [%0], {%1, %2, %3, %4};"
                 :: "l"(p), "f"(a), "f"(b), "f"(c), "f"(d) : "memory");
}
__device__ __forceinline__ void cp16(void* dst_smem, const void* src)
{
    uint32_t d = (uint32_t)__cvta_generic_to_shared(dst_smem);
    asm volatile("cp.async.ca.shared.global [%0], [%1], 16;"
                 :: "r"(d), "l"(src) : "memory");
}
__device__ __forceinline__ void cp_commit()
{
    asm volatile("cp.async.commit_group;" ::: "memory");
}
template <int N>
__device__ __forceinline__ void cp_wait()
{
    asm volatile("cp.async.wait_group %0;" :: "n"(N) : "memory");
}

// ---------------------------------------------------------------------------
__global__ __launch_bounds__(256) void split_w(
    const float* __restrict__ W, __nv_bfloat16* __restrict__ hi,
    __nv_bfloat16* __restrict__ lo, int n)
{
    int i = blockIdx.x * 256 + threadIdx.x;
    if (i < n) {
        float v = W[i];
        __nv_bfloat16 h = __float2bfloat16_rn(v);
        hi[i] = h;
        lo[i] = __float2bfloat16_rn(v - __bfloat162float(h));
    }
}

template <bool TANH>
__global__ __launch_bounds__(256) void split_x(
    const float* __restrict__ src,
    __nv_bfloat16* __restrict__ hi, __nv_bfloat16* __restrict__ lo)
{
    const long long e = ((long long)blockIdx.x * 256 + threadIdx.x) * 4;
    float4 f = *(const float4*)(src + e);
    if (TANH) {
        f.x = tanhf(f.x); f.y = tanhf(f.y);
        f.z = tanhf(f.z); f.w = tanhf(f.w);
    }
    __nv_bfloat16 h0 = __float2bfloat16_rn(f.x);
    __nv_bfloat16 h1 = __float2bfloat16_rn(f.y);
    __nv_bfloat16 h2 = __float2bfloat16_rn(f.z);
    __nv_bfloat16 h3 = __float2bfloat16_rn(f.w);
    __nv_bfloat162 H0(h0, h1), H1(h2, h3);
    __nv_bfloat162 L0(__float2bfloat16_rn(f.x - __bfloat162float(h0)),
                      __float2bfloat16_rn(f.y - __bfloat162float(h1)));
    __nv_bfloat162 L1(__float2bfloat16_rn(f.z - __bfloat162float(h2)),
                      __float2bfloat16_rn(f.w - __bfloat162float(h3)));
    *(__nv_bfloat162*)(hi + e)     = H0;
    *(__nv_bfloat162*)(hi + e + 2) = H1;
    *(__nv_bfloat162*)(lo + e)     = L0;
    *(__nv_bfloat162*)(lo + e + 2) = L1;
}

// ---------------------------------------------------------------------------
// Outer tensor-core GEMM (wmma bf16, 3-pass split, cp.async 2-stage) — R14.
// ---------------------------------------------------------------------------
__global__ __launch_bounds__(256) void wmma_gemm(
    const __nv_bfloat16* __restrict__ Whi, const __nv_bfloat16* __restrict__ Wlo,
    const __nv_bfloat16* __restrict__ Xhi, const __nv_bfloat16* __restrict__ Xlo,
    float* __restrict__ Cb, long long cstride)
{
    extern __shared__ __align__(16) char sm[];

    const int tid = threadIdx.x;
    const int wid = tid >> 5;
    const int m0  = blockIdx.x * 128;
    const int t   = blockIdx.y;
    const int wm  = wid >> 1;
    const int wn  = wid & 1;

    const __nv_bfloat16* WhP = Whi + (size_t)m0 * KDIM;
    const __nv_bfloat16* WlP = Wlo + (size_t)m0 * KDIM;
    const __nv_bfloat16* Xh  = Xhi + (size_t)t * HB;
    const __nv_bfloat16* Xl  = Xlo + (size_t)t * HB;

    wmma::fragment<wmma::accumulator, 16, 16, 16, float> acc[2][4];
#pragma unroll
    for (int i = 0; i < 2; i++)
#pragma unroll
        for (int j = 0; j < 4; j++) wmma::fill_fragment(acc[i][j], 0.0f);

    auto load_chunk = [&](int k0, int s) {
        char* base = sm + s * STG_BYTES;
        char* Ahp = base;
        char* Alp = base + A_BYTES;
        char* Bhp = base + 2 * A_BYTES;
        char* Blp = base + 2 * A_BYTES + B_BYTES;
#pragma unroll
        for (int q = 0; q < 2; q++) {
            const int v = tid + q * 256;
            const int row = v >> 2, kq = (v & 3) * 8;
            cp16(Ahp + row * (KPA * 2) + kq * 2,
                 WhP + (size_t)row * KDIM + k0 + kq);
            cp16(Alp + row * (KPA * 2) + kq * 2,
                 WlP + (size_t)row * KDIM + k0 + kq);
        }
#pragma unroll
        for (int q = 0; q < 2; q++) {
            const int u = tid + q * 256;
            const int krow = u >> 4, bcol = (u & 15) * 8;
            cp16(Bhp + krow * (KPB * 2) + bcol * 2,
                 Xh + (size_t)(k0 + krow) * BB + bcol);
            cp16(Blp + krow * (KPB * 2) + bcol * 2,
                 Xl + (size_t)(k0 + krow) * BB + bcol);
        }
        cp_commit();
    };

    load_chunk(0, 0);

    for (int c = 0; c < KDIM / CH; c++) {
        const int s = c & 1;
        if (c + 1 < KDIM / CH) {
            load_chunk((c + 1) * CH, s ^ 1);
            cp_wait<1>();
        } else {
            cp_wait<0>();
        }
        __syncthreads();

        char* base = sm + s * STG_BYTES;
        __nv_bfloat16 (*Ah)[KPA] = (__nv_bfloat16(*)[KPA])(base);
        __nv_bfloat16 (*Al)[KPA] = (__nv_bfloat16(*)[KPA])(base + A_BYTES);
        __nv_bfloat16 (*Bh)[KPB] = (__nv_bfloat16(*)[KPB])(base + 2 * A_BYTES);
        __nv_bfloat16 (*Bl)[KPB] =
            (__nv_bfloat16(*)[KPB])(base + 2 * A_BYTES + B_BYTES);

#pragma unroll
        for (int kk = 0; kk < CH; kk += 16) {
            wmma::fragment<wmma::matrix_a, 16, 16, 16, __nv_bfloat16,
                           wmma::row_major> fah[2], fal[2];
            wmma::fragment<wmma::matrix_b, 16, 16, 16, __nv_bfloat16,
                           wmma::row_major> fbh[4], fbl[4];
#pragma unroll
            for (int i = 0; i < 2; i++) {
                wmma::load_matrix_sync(fah[i], &Ah[wm * 32 + i * 16][kk], KPA);
                wmma::load_matrix_sync(fal[i], &Al[wm * 32 + i * 16][kk], KPA);
            }
#pragma unroll
            for (int j = 0; j < 4; j++) {
                wmma::load_matrix_sync(fbh[j], &Bh[kk][wn * 64 + j * 16], KPB);
                wmma::load_matrix_sync(fbl[j], &Bl[kk][wn * 64 + j * 16], KPB);
            }
#pragma unroll
            for (int i = 0; i < 2; i++)
#pragma unroll
                for (int j = 0; j < 4; j++) {
                    wmma::mma_sync(acc[i][j], fah[i], fbh[j], acc[i][j]);
                    wmma::mma_sync(acc[i][j], fah[i], fbl[j], acc[i][j]);
                    wmma::mma_sync(acc[i][j], fal[i], fbh[j], acc[i][j]);
                }
        }
        __syncthreads();
    }

    float* C = Cb + (long long)t * cstride;
#pragma unroll
    for (int i = 0; i < 2; i++)
#pragma unroll
        for (int j = 0; j < 4; j++)
            wmma::store_matrix_sync(
                C + (long long)(m0 + wm * 32 + i * 16) * BB + wn * 64 + j * 16,
                acc[i][j], BB, wmma::mem_row_major);
}

__global__ __launch_bounds__(256) void bias_add4(
    float* __restrict__ C, const float* __restrict__ bias)
{
    const long long e = ((long long)blockIdx.x * 256 + threadIdx.x) * 4;
    const float bv = bias[(e >> 7) & 1023];
    float4 v = *(float4*)(C + e);
    v.x += bv; v.y += bv; v.z += bv; v.w += bv;
    *(float4*)(C + e) = v;
}

// ---------------------------------------------------------------------------
// Pipelined tensor-core recurrence step:
//   W slice (64m x 128k, hi+lo) cp.async'd ONCE into smem;
//   B (tanh+split of h chunk) double-buffered; ONE sync per chunk;
//   per chunk: LDG(c+1) -> MMA(c) -> stage(c+1) -> sync.
// ---------------------------------------------------------------------------
__global__ __launch_bounds__(256) void rnn_step_tc(
    const __nv_bfloat16* __restrict__ Whi, const __nv_bfloat16* __restrict__ Wlo,
    const float* __restrict__ src, float* __restrict__ dst,
    const float* __restrict__ bias, int do_tanh)
{
    extern __shared__ __align__(16) char sm[];
    __nv_bfloat16 (*Wh)[136] = (__nv_bfloat16(*)[136])(sm);
    __nv_bfloat16 (*Wl)[136] = (__nv_bfloat16(*)[136])(sm + S_W_BYTES);

    const int tid = threadIdx.x;
    const int wid = tid >> 5;
    const int m0  = blockIdx.x * 64;
    const int k0  = blockIdx.y * 128;
    const int wm  = wid >> 1;        // 0..3 -> rows wm*16
    const int wn  = wid & 1;         // 0..1 -> cols wn*64

    const __nv_bfloat16* WhP = Whi + (size_t)m0 * HID_F + k0;
    const __nv_bfloat16* WlP = Wlo + (size_t)m0 * HID_F + k0;
    const float*         Hs  = src + (size_t)k0 * BB;

    wmma::fragment<wmma::accumulator, 16, 16, 16, float> acc[4];
#pragma unroll
    for (int j = 0; j < 4; j++) wmma::fill_fragment(acc[j], 0.0f);

    // prologue: stream whole W slice (hi+lo) via cp.async
#pragma unroll
    for (int q = 0; q < 4; q++) {
        const int v = tid + q * 256;             // 0..1023
        const int row = v >> 4, kq = (v & 15) * 8;
        cp16((char*)&Wh[row][kq], WhP + (size_t)row * HID_F + kq);
        cp16((char*)&Wl[row][kq], WlP + (size_t)row * HID_F + kq);
    }
    cp_commit();

    float4 bx[4];
    auto load_regs = [&](int c0) {
#pragma unroll
        for (int q = 0; q < 4; q++) {
            const int u = tid + q * 256;
            const int krow = u >> 5;             // 0..31
            const int bcol = (u & 31) * 4;       // 0..124
            bx[q] = *(const float4*)(Hs + (size_t)(c0 + krow) * BB + bcol);
        }
    };

    auto stage_B = [&](int s) {
        char* bb = sm + 2 * S_W_BYTES + s * S_STG;
        __nv_bfloat16 (*Bh)[136] = (__nv_bfloat16(*)[136])(bb);
        __nv_bfloat16 (*Bl)[136] = (__nv_bfloat16(*)[136])(bb + S_B_BYTES);
#pragma unroll
        for (int q = 0; q < 4; q++) {
            const int u = tid + q * 256;
            const int krow = u >> 5, bcol = (u & 31) * 4;
            float4 f = bx[q];
            if (do_tanh) {
                f.x = tanhf(f.x); f.y = tanhf(f.y);
                f.z = tanhf(f.z); f.w = tanhf(f.w);
            }
            __nv_bfloat16 h0 = __float2bfloat16_rn(f.x);
            __nv_bfloat16 h1 = __float2bfloat16_rn(f.y);
            __nv_bfloat16 h2 = __float2bfloat16_rn(f.z);
            __nv_bfloat16 h3 = __float2bfloat16_rn(f.w);
            *(__nv_bfloat162*)&Bh[krow][bcol]     = __nv_bfloat162(h0, h1);
            *(__nv_bfloat162*)&Bh[krow][bcol + 2] = __nv_bfloat162(h2, h3);
            *(__nv_bfloat162*)&Bl[krow][bcol] =
                __nv_bfloat162(__float2bfloat16_rn(f.x - __bfloat162float(h0)),
                               __float2bfloat16_rn(f.y - __bfloat162float(h1)));
            *(__nv_bfloat162*)&Bl[krow][bcol + 2] =
                __nv_bfloat162(__float2bfloat16_rn(f.z - __bfloat162float(h2)),
                               __float2bfloat16_rn(f.w - __bfloat162float(h3)));
        }
    };

    load_regs(0);
    stage_B(0);          // does not touch W
    cp_wait<0>();        // W resident
    __syncthreads();

    for (int c = 0; c < 4; c++) {
        const int s = c & 1;
        if (c < 3) load_regs((c + 1) * 32);      // long-latency LDG first

        // MMA on chunk c (reads W smem + B stage s)
        char* bb = sm + 2 * S_W_BYTES + s * S_STG;
        __nv_bfloat16 (*Bh)[136] = (__nv_bfloat16(*)[136])(bb);
        __nv_bfloat16 (*Bl)[136] = (__nv_bfloat16(*)[136])(bb + S_B_BYTES);
#pragma unroll
        for (int kk = 0; kk < 32; kk += 16) {
            wmma::fragment<wmma::matrix_a, 16, 16, 16, __nv_bfloat16,
                           wmma::row_major> fah, fal;
            wmma::fragment<wmma::matrix_b, 16, 16, 16, __nv_bfloat16,
                           wmma::row_major> fbh[4], fbl[4];
            wmma::load_matrix_sync(fah, &Wh[wm * 16][c * 32 + kk], 136);
            wmma::load_matrix_sync(fal, &Wl[wm * 16][c * 32 + kk], 136);
#pragma unroll
            for (int j = 0; j < 4; j++) {
                wmma::load_matrix_sync(fbh[j], &Bh[kk][wn * 64 + j * 16], 136);
                wmma::load_matrix_sync(fbl[j], &Bl[kk][wn * 64 + j * 16], 136);
            }
#pragma unroll
            for (int j = 0; j < 4; j++) {
                wmma::mma_sync(acc[j], fah, fbh[j], acc[j]);
                wmma::mma_sync(acc[j], fah, fbl[j], acc[j]);
                wmma::mma_sync(acc[j], fal, fbh[j], acc[j]);
            }
        }

        if (c < 3) stage_B(s ^ 1);   // overlaps with MMA in issue stream
        __syncthreads();
    }

    // epilogue: frags -> smem (reuse W region) -> red.add.v4 with bh/8
    float (*Ep)[132] = (float(*)[132])sm;
#pragma unroll
    for (int j = 0; j < 4; j++)
        wmma::store_matrix_sync(&Ep[wm * 16][wn * 64 + j * 16], acc[j], 132,
                                wmma::mem_row_major);
    __syncthreads();

#pragma unroll
    for (int it = 0; it < 8; it++) {
        const int idx = tid + it * 256;
        const int row = idx >> 5;
        const int col = (idx & 31) * 4;
        float4 v = *(const float4*)&Ep[row][col];
        const float bv = bias[m0 + row] * 0.125f;
        red_add_v4(dst + (size_t)(m0 + row) * BB + col,
                   v.x + bv, v.y + bv, v.z + bv, v.w + bv);
    }
}

// h_final = tanh(S[T-1])
__global__ __launch_bounds__(256) void copy_final(float* __restrict__ out)
{
    const int idx = blockIdx.x * 256 + threadIdx.x;
    out[(long long)TT * OUT_F * BB + idx] =
        tanhf(g_S[(long long)(TT - 1) * HB + idx]);
}

// ---------------------------------------------------------------------------
extern "C" void kernel_launch(void* const* d_in, const int* in_sizes, int n_in,
                              void* d_out, int out_size)
{
    (void)in_sizes; (void)n_in; (void)out_size;
    const float* inputs = (const float*)d_in[0];
    const float* h_prev = (const float*)d_in[1];
    const float* Wxh    = (const float*)d_in[2];
    const float* Whh    = (const float*)d_in[3];
    const float* Why    = (const float*)d_in[4];
    const float* bh     = (const float*)d_in[5];
    const float* by     = (const float*)d_in[6];
    float* out = (float*)d_out;

    float* pS = nullptr;
    __nv_bfloat16 *pXh, *pXl, *pW1h, *pW1l, *pW2h, *pW2l, *pWHh, *pWHl;
    cudaGetSymbolAddress((void**)&pS,  g_S);
    cudaGetSymbolAddress((void**)&pXh, g_Xhi);
    cudaGetSymbolAddress((void**)&pXl, g_Xlo);
    cudaGetSymbolAddress((void**)&pW1h, g_W1hi);
    cudaGetSymbolAddress((void**)&pW1l, g_W1lo);
    cudaGetSymbolAddress((void**)&pW2h, g_W2hi);
    cudaGetSymbolAddress((void**)&pW2l, g_W2lo);
    cudaGetSymbolAddress((void**)&pWHh, g_WHhi);
    cudaGetSymbolAddress((void**)&pWHl, g_WHlo);

    cudaFuncSetAttribute(wmma_gemm,
                         cudaFuncAttributeMaxDynamicSharedMemorySize, GSMEM);
    cudaFuncSetAttribute(rnn_step_tc,
                         cudaFuncAttributeMaxDynamicSharedMemorySize, SSMEM);

    // weight splits
    split_w<<<4096, 256>>>(Wxh, pW1h, pW1l, HID_F * IN_F);
    split_w<<<4096, 256>>>(Whh, pWHh, pWHl, HID_F * HID_F);
    split_w<<<4096, 256>>>(Why, pW2h, pW2l, OUT_F * HID_F);

    // 1) split inputs once, then S[t] = Wxh @ x_t
    split_x<false><<<TT * HB / 1024, 256>>>(inputs, pXh, pXl);
    wmma_gemm<<<dim3(8, TT), 256, GSMEM>>>(pW1h, pW1l, pXh, pXl, pS,
                                           (long long)HB);

    // 2) serial recurrence (pipelined tensor-core step, 1 launch/step)
    for (int t = 0; t < TT; ++t) {
        const float* src = (t == 0) ? h_prev : (pS + (long long)(t - 1) * HB);
        rnn_step_tc<<<dim3(16, 8), 256, SSMEM>>>(pWHh, pWHl, src,
                                                 pS + (long long)t * HB,
                                                 bh, t == 0 ? 0 : 1);
    }

    // 3) split tanh(S) once, then y_t = Why @ h_t, + by
    split_x<true><<<TT * HB / 1024, 256>>>(pS, pXh, pXl);
    wmma_gemm<<<dim3(8, TT), 256, GSMEM>>>(pW2h, pW2l, pXh, pXl, out,
                                           (long long)OUT_F * BB);
    bias_add4<<<TT * OUT_F * BB / 1024, 256>>>(out, by);

    // 4) h_final
    copy_final<<<512, 256>>>(out);
}

// round 17
// speedup vs baseline: 1.8452x; 1.8452x over previous
#include <cuda_runtime.h>
#include <cuda_bf16.h>
#include <mma.h>
#include <math.h>
#include <stdint.h>

using namespace nvcuda;

#define TT    256
#define IN_F  1024
#define HID_F 1024
#define OUT_F 1024
#define BB    128
#define HB    (HID_F * BB)
#define KDIM  1024
#define CH    32          // K chunk (outer GEMMs)
#define KPA   40          // outer GEMM A smem k-pitch
#define KPB   136         // B smem pitch (elements)
#define SCH   32          // K chunk (step kernel)
#define NSTG  4           // outer GEMM pipeline stages

// outer gemm dynamic smem: NSTG stages x (Ah+Al+Bh+Bl)
#define A_BYTES   (128 * KPA * 2)             // 10240
#define B_BYTES   (CH * KPB * 2)              // 8704
#define STG_BYTES (2 * A_BYTES + 2 * B_BYTES) // 37888
#define GSMEM     (NSTG * STG_BYTES)          // 151552

// Scratch (__device__ globals; no allocations allowed)
__device__ float g_S[(size_t)TT * HB];
__device__ __nv_bfloat16 g_Xhi[(size_t)TT * HB];
__device__ __nv_bfloat16 g_Xlo[(size_t)TT * HB];
__device__ __nv_bfloat16 g_W1hi[(size_t)HID_F * IN_F];
__device__ __nv_bfloat16 g_W1lo[(size_t)HID_F * IN_F];
__device__ __nv_bfloat16 g_W2hi[(size_t)OUT_F * HID_F];
__device__ __nv_bfloat16 g_W2lo[(size_t)OUT_F * HID_F];
__device__ __nv_bfloat16 g_WHhi[(size_t)HID_F * HID_F];
__device__ __nv_bfloat16 g_WHlo[(size_t)HID_F * HID_F];

// ---------------------------------------------------------------------------
__device__ __forceinline__ void red_add_v4(float* p, float a, float b,
                                           float c, float d)
{
    asm volatile("red.global.add.v4.f32 [%0], {%1, %2, %3, %4};"
                 :: "l"(p), "f"(a), "f"(b), "f"(c), "f"(d) : "memory");
}
__device__ __forceinline__ void cp16(void* dst_smem, const void* src)
{
    uint32_t d = (uint32_t)__cvta_generic_to_shared(dst_smem);
    asm volatile("cp.async.ca.shared.global [%0], [%1], 16;"
                 :: "r"(d), "l"(src) : "memory");
}
__device__ __forceinline__ void cp_commit()
{
    asm volatile("cp.async.commit_group;" ::: "memory");
}
template <int N>
__device__ __forceinline__ void cp_wait()
{
    asm volatile("cp.async.wait_group %0;" :: "n"(N) : "memory");
}

// ---------------------------------------------------------------------------
__global__ __launch_bounds__(256) void split_w(
    const float* __restrict__ W, __nv_bfloat16* __restrict__ hi,
    __nv_bfloat16* __restrict__ lo, int n)
{
    int i = blockIdx.x * 256 + threadIdx.x;
    if (i < n) {
        float v = W[i];
        __nv_bfloat16 h = __float2bfloat16_rn(v);
        hi[i] = h;
        lo[i] = __float2bfloat16_rn(v - __bfloat162float(h));
    }
}

template <bool TANH>
__global__ __launch_bounds__(256) void split_x(
    const float* __restrict__ src,
    __nv_bfloat16* __restrict__ hi, __nv_bfloat16* __restrict__ lo)
{
    const long long e = ((long long)blockIdx.x * 256 + threadIdx.x) * 4;
    float4 f = *(const float4*)(src + e);
    if (TANH) {
        f.x = tanhf(f.x); f.y = tanhf(f.y);
        f.z = tanhf(f.z); f.w = tanhf(f.w);
    }
    __nv_bfloat16 h0 = __float2bfloat16_rn(f.x);
    __nv_bfloat16 h1 = __float2bfloat16_rn(f.y);
    __nv_bfloat16 h2 = __float2bfloat16_rn(f.z);
    __nv_bfloat16 h3 = __float2bfloat16_rn(f.w);
    __nv_bfloat162 H0(h0, h1), H1(h2, h3);
    __nv_bfloat162 L0(__float2bfloat16_rn(f.x - __bfloat162float(h0)),
                      __float2bfloat16_rn(f.y - __bfloat162float(h1)));
    __nv_bfloat162 L1(__float2bfloat16_rn(f.z - __bfloat162float(h2)),
                      __float2bfloat16_rn(f.w - __bfloat162float(h3)));
    *(__nv_bfloat162*)(hi + e)     = H0;
    *(__nv_bfloat162*)(hi + e + 2) = H1;
    *(__nv_bfloat162*)(lo + e)     = L0;
    *(__nv_bfloat162*)(lo + e + 2) = L1;
}

// ---------------------------------------------------------------------------
// Outer tensor-core GEMM (wmma bf16, 3-pass split), cp.async 4-stage ring.
// ---------------------------------------------------------------------------
__global__ __launch_bounds__(256) void wmma_gemm(
    const __nv_bfloat16* __restrict__ Whi, const __nv_bfloat16* __restrict__ Wlo,
    const __nv_bfloat16* __restrict__ Xhi, const __nv_bfloat16* __restrict__ Xlo,
    float* __restrict__ Cb, long long cstride)
{
    extern __shared__ __align__(16) char sm[];

    const int tid = threadIdx.x;
    const int wid = tid >> 5;
    const int m0  = blockIdx.x * 128;
    const int t   = blockIdx.y;
    const int wm  = wid >> 1;
    const int wn  = wid & 1;

    const __nv_bfloat16* WhP = Whi + (size_t)m0 * KDIM;
    const __nv_bfloat16* WlP = Wlo + (size_t)m0 * KDIM;
    const __nv_bfloat16* Xh  = Xhi + (size_t)t * HB;
    const __nv_bfloat16* Xl  = Xlo + (size_t)t * HB;

    wmma::fragment<wmma::accumulator, 16, 16, 16, float> acc[2][4];
#pragma unroll
    for (int i = 0; i < 2; i++)
#pragma unroll
        for (int j = 0; j < 4; j++) wmma::fill_fragment(acc[i][j], 0.0f);

    auto load_chunk = [&](int k0, int s) {
        char* base = sm + s * STG_BYTES;
        char* Ahp = base;
        char* Alp = base + A_BYTES;
        char* Bhp = base + 2 * A_BYTES;
        char* Blp = base + 2 * A_BYTES + B_BYTES;
#pragma unroll
        for (int q = 0; q < 2; q++) {
            const int v = tid + q * 256;
            const int row = v >> 2, kq = (v & 3) * 8;
            cp16(Ahp + row * (KPA * 2) + kq * 2,
                 WhP + (size_t)row * KDIM + k0 + kq);
            cp16(Alp + row * (KPA * 2) + kq * 2,
                 WlP + (size_t)row * KDIM + k0 + kq);
        }
#pragma unroll
        for (int q = 0; q < 2; q++) {
            const int u = tid + q * 256;
            const int krow = u >> 4, bcol = (u & 15) * 8;
            cp16(Bhp + krow * (KPB * 2) + bcol * 2,
                 Xh + (size_t)(k0 + krow) * BB + bcol);
            cp16(Blp + krow * (KPB * 2) + bcol * 2,
                 Xl + (size_t)(k0 + krow) * BB + bcol);
        }
        cp_commit();
    };

    const int NCH = KDIM / CH;                 // 32 chunks
    load_chunk(0, 0);
    load_chunk(CH, 1);
    load_chunk(2 * CH, 2);

    for (int c = 0; c < NCH; c++) {
        // ensure chunk c is resident (tail needs tighter waits)
        if (c <= NCH - 3)      cp_wait<2>();
        else if (c == NCH - 2) cp_wait<1>();
        else                   cp_wait<0>();
        __syncthreads();

        char* base = sm + (c & (NSTG - 1)) * STG_BYTES;
        __nv_bfloat16 (*Ah)[KPA] = (__nv_bfloat16(*)[KPA])(base);
        __nv_bfloat16 (*Al)[KPA] = (__nv_bfloat16(*)[KPA])(base + A_BYTES);
        __nv_bfloat16 (*Bh)[KPB] = (__nv_bfloat16(*)[KPB])(base + 2 * A_BYTES);
        __nv_bfloat16 (*Bl)[KPB] =
            (__nv_bfloat16(*)[KPB])(base + 2 * A_BYTES + B_BYTES);

#pragma unroll
        for (int kk = 0; kk < CH; kk += 16) {
            wmma::fragment<wmma::matrix_a, 16, 16, 16, __nv_bfloat16,
                           wmma::row_major> fah[2], fal[2];
            wmma::fragment<wmma::matrix_b, 16, 16, 16, __nv_bfloat16,
                           wmma::row_major> fbh[4], fbl[4];
#pragma unroll
            for (int i = 0; i < 2; i++) {
                wmma::load_matrix_sync(fah[i], &Ah[wm * 32 + i * 16][kk], KPA);
                wmma::load_matrix_sync(fal[i], &Al[wm * 32 + i * 16][kk], KPA);
            }
#pragma unroll
            for (int j = 0; j < 4; j++) {
                wmma::load_matrix_sync(fbh[j], &Bh[kk][wn * 64 + j * 16], KPB);
                wmma::load_matrix_sync(fbl[j], &Bl[kk][wn * 64 + j * 16], KPB);
            }
#pragma unroll
            for (int i = 0; i < 2; i++)
#pragma unroll
                for (int j = 0; j < 4; j++) {
                    wmma::mma_sync(acc[i][j], fah[i], fbh[j], acc[i][j]);
                    wmma::mma_sync(acc[i][j], fah[i], fbl[j], acc[i][j]);
                    wmma::mma_sync(acc[i][j], fal[i], fbh[j], acc[i][j]);
                }
        }

        // refill the stage we just finished reading (3 chunks ahead);
        // safe: all warps passed the sync at top of this iteration, and the
        // target stage (c+3)&3 == (c-1)&3 was fully consumed last iteration.
        if (c + 3 < NCH) load_chunk((c + 3) * CH, (c + 3) & (NSTG - 1));
        __syncthreads();
    }

    float* C = Cb + (long long)t * cstride;
#pragma unroll
    for (int i = 0; i < 2; i++)
#pragma unroll
        for (int j = 0; j < 4; j++)
            wmma::store_matrix_sync(
                C + (long long)(m0 + wm * 32 + i * 16) * BB + wn * 64 + j * 16,
                acc[i][j], BB, wmma::mem_row_major);
}

__global__ __launch_bounds__(256) void bias_add4(
    float* __restrict__ C, const float* __restrict__ bias)
{
    const long long e = ((long long)blockIdx.x * 256 + threadIdx.x) * 4;
    const float bv = bias[(e >> 7) & 1023];
    float4 v = *(float4*)(C + e);
    v.x += bv; v.y += bv; v.z += bv; v.w += bv;
    *(float4*)(C + e) = v;
}

// ---------------------------------------------------------------------------
// Tensor-core recurrence step — EXACT R13 version (proven ~8.6 us/step).
// ---------------------------------------------------------------------------
__global__ __launch_bounds__(256) void rnn_step_tc(
    const __nv_bfloat16* __restrict__ Whi, const __nv_bfloat16* __restrict__ Wlo,
    const float* __restrict__ src, float* __restrict__ dst,
    const float* __restrict__ bias, int do_tanh)
{
    __shared__ __align__(32) char sm[33792];
    __nv_bfloat16 (*Ah)[40]  = (__nv_bfloat16(*)[40])(sm);
    __nv_bfloat16 (*Al)[40]  = (__nv_bfloat16(*)[40])(sm + 5120);
    __nv_bfloat16 (*Bh)[136] = (__nv_bfloat16(*)[136])(sm + 10240);
    __nv_bfloat16 (*Bl)[136] = (__nv_bfloat16(*)[136])(sm + 18944);

    const int tid = threadIdx.x;
    const int wid = tid >> 5;
    const int m0  = blockIdx.x * 64;
    const int k0  = blockIdx.y * 128;
    const int wm  = wid >> 1;
    const int wn  = wid & 1;

    const __nv_bfloat16* WhP = Whi + (size_t)m0 * HID_F + k0;
    const __nv_bfloat16* WlP = Wlo + (size_t)m0 * HID_F + k0;
    const float*         Hs  = src + (size_t)k0 * BB;

    wmma::fragment<wmma::accumulator, 16, 16, 16, float> acc[4];
#pragma unroll
    for (int j = 0; j < 4; j++) wmma::fill_fragment(acc[j], 0.0f);

    uint4  aH, aL;
    float4 bx[4];
    const int arow = tid >> 2, akq = (tid & 3) * 8;

    auto load_regs = [&](int c0) {
        aH = *(const uint4*)(WhP + (size_t)arow * HID_F + c0 + akq);
        aL = *(const uint4*)(WlP + (size_t)arow * HID_F + c0 + akq);
#pragma unroll
        for (int q = 0; q < 4; q++) {
            const int u = tid + q * 256;
            const int krow = u >> 5;
            const int bcol = (u & 31) * 4;
            bx[q] = *(const float4*)(Hs + (size_t)(c0 + krow) * BB + bcol);
        }
    };

    load_regs(0);

    for (int c = 0; c < 128 / SCH; c++) {
        *(uint4*)&Ah[arow][akq] = aH;
        *(uint4*)&Al[arow][akq] = aL;
#pragma unroll
        for (int q = 0; q < 4; q++) {
            const int u = tid + q * 256;
            const int krow = u >> 5, bcol = (u & 31) * 4;
            float4 f = bx[q];
            if (do_tanh) {
                f.x = tanhf(f.x); f.y = tanhf(f.y);
                f.z = tanhf(f.z); f.w = tanhf(f.w);
            }
            __nv_bfloat16 h0 = __float2bfloat16_rn(f.x);
            __nv_bfloat16 h1 = __float2bfloat16_rn(f.y);
            __nv_bfloat16 h2 = __float2bfloat16_rn(f.z);
            __nv_bfloat16 h3 = __float2bfloat16_rn(f.w);
            *(__nv_bfloat162*)&Bh[krow][bcol]     = __nv_bfloat162(h0, h1);
            *(__nv_bfloat162*)&Bh[krow][bcol + 2] = __nv_bfloat162(h2, h3);
            *(__nv_bfloat162*)&Bl[krow][bcol] =
                __nv_bfloat162(__float2bfloat16_rn(f.x - __bfloat162float(h0)),
                               __float2bfloat16_rn(f.y - __bfloat162float(h1)));
            *(__nv_bfloat162*)&Bl[krow][bcol + 2] =
                __nv_bfloat162(__float2bfloat16_rn(f.z - __bfloat162float(h2)),
                               __float2bfloat16_rn(f.w - __bfloat162float(h3)));
        }
        __syncthreads();

        if (c + 1 < 128 / SCH) load_regs((c + 1) * SCH);

#pragma unroll
        for (int kk = 0; kk < SCH; kk += 16) {
            wmma::fragment<wmma::matrix_a, 16, 16, 16, __nv_bfloat16,
                           wmma::row_major> fah, fal;
            wmma::fragment<wmma::matrix_b, 16, 16, 16, __nv_bfloat16,
                           wmma::row_major> fbh[4], fbl[4];
            wmma::load_matrix_sync(fah, &Ah[wm * 16][kk], 40);
            wmma::load_matrix_sync(fal, &Al[wm * 16][kk], 40);
#pragma unroll
            for (int j = 0; j < 4; j++) {
                wmma::load_matrix_sync(fbh[j], &Bh[kk][wn * 64 + j * 16], 136);
                wmma::load_matrix_sync(fbl[j], &Bl[kk][wn * 64 + j * 16], 136);
            }
#pragma unroll
            for (int j = 0; j < 4; j++) {
                wmma::mma_sync(acc[j], fah, fbh[j], acc[j]);
                wmma::mma_sync(acc[j], fah, fbl[j], acc[j]);
                wmma::mma_sync(acc[j], fal, fbh[j], acc[j]);
            }
        }
        __syncthreads();
    }

    float (*Ep)[132] = (float(*)[132])sm;
#pragma unroll
    for (int j = 0; j < 4; j++)
        wmma::store_matrix_sync(&Ep[wm * 16][wn * 64 + j * 16], acc[j], 132,
                                wmma::mem_row_major);
    __syncthreads();

#pragma unroll
    for (int it = 0; it < 8; it++) {
        const int idx = tid + it * 256;
        const int row = idx >> 5;
        const int col = (idx & 31) * 4;
        float4 v = *(const float4*)&Ep[row][col];
        const float bv = bias[m0 + row] * 0.125f;
        red_add_v4(dst + (size_t)(m0 + row) * BB + col,
                   v.x + bv, v.y + bv, v.z + bv, v.w + bv);
    }
}

// h_final = tanh(S[T-1])
__global__ __launch_bounds__(256) void copy_final(float* __restrict__ out)
{
    const int idx = blockIdx.x * 256 + threadIdx.x;
    out[(long long)TT * OUT_F * BB + idx] =
        tanhf(g_S[(long long)(TT - 1) * HB + idx]);
}

// ---------------------------------------------------------------------------
extern "C" void kernel_launch(void* const* d_in, const int* in_sizes, int n_in,
                              void* d_out, int out_size)
{
    (void)in_sizes; (void)n_in; (void)out_size;
    const float* inputs = (const float*)d_in[0];
    const float* h_prev = (const float*)d_in[1];
    const float* Wxh    = (const float*)d_in[2];
    const float* Whh    = (const float*)d_in[3];
    const float* Why    = (const float*)d_in[4];
    const float* bh     = (const float*)d_in[5];
    const float* by     = (const float*)d_in[6];
    float* out = (float*)d_out;

    float* pS = nullptr;
    __nv_bfloat16 *pXh, *pXl, *pW1h, *pW1l, *pW2h, *pW2l, *pWHh, *pWHl;
    cudaGetSymbolAddress((void**)&pS,  g_S);
    cudaGetSymbolAddress((void**)&pXh, g_Xhi);
    cudaGetSymbolAddress((void**)&pXl, g_Xlo);
    cudaGetSymbolAddress((void**)&pW1h, g_W1hi);
    cudaGetSymbolAddress((void**)&pW1l, g_W1lo);
    cudaGetSymbolAddress((void**)&pW2h, g_W2hi);
    cudaGetSymbolAddress((void**)&pW2l, g_W2lo);
    cudaGetSymbolAddress((void**)&pWHh, g_WHhi);
    cudaGetSymbolAddress((void**)&pWHl, g_WHlo);

    cudaFuncSetAttribute(wmma_gemm,
                         cudaFuncAttributeMaxDynamicSharedMemorySize, GSMEM);

    // weight splits
    split_w<<<4096, 256>>>(Wxh, pW1h, pW1l, HID_F * IN_F);
    split_w<<<4096, 256>>>(Whh, pWHh, pWHl, HID_F * HID_F);
    split_w<<<4096, 256>>>(Why, pW2h, pW2l, OUT_F * HID_F);

    // 1) split inputs once, then S[t] = Wxh @ x_t
    split_x<false><<<TT * HB / 1024, 256>>>(inputs, pXh, pXl);
    wmma_gemm<<<dim3(8, TT), 256, GSMEM>>>(pW1h, pW1l, pXh, pXl, pS,
                                           (long long)HB);

    // 2) serial recurrence (R13 tensor-core step, 1 launch/step)
    for (int t = 0; t < TT; ++t) {
        const float* src = (t == 0) ? h_prev : (pS + (long long)(t - 1) * HB);
        rnn_step_tc<<<dim3(16, 8), 256>>>(pWHh, pWHl, src,
                                          pS + (long long)t * HB,
                                          bh, t == 0 ? 0 : 1);
    }

    // 3) split tanh(S) once, then y_t = Why @ h_t, + by
    split_x<true><<<TT * HB / 1024, 256>>>(pS, pXh, pXl);
    wmma_gemm<<<dim3(8, TT), 256, GSMEM>>>(pW2h, pW2l, pXh, pXl, out,
                                           (long long)OUT_F * BB);
    bias_add4<<<TT * OUT_F * BB / 1024, 256>>>(out, by);

    // 4) h_final
    copy_final<<<512, 256>>>(out);
}